// round 8
// baseline (speedup 1.0000x reference)
#include <cuda_runtime.h>
#include <stdint.h>

#define N1 8192
#define N2 8192
#define D  1024
#define C  128
#define NTY 8

// packed dual-fp32 FMA: d.lo += a.lo*b.lo, d.hi += a.hi*b.hi (SASS FFMA2, 2x fp32 tput)
#define FMA_F32X2(d, a, b) \
    asm("fma.rn.f32x2 %0, %1, %2, %0;" : "+l"(d) : "l"(a), "l"(b))

// ---------------- device scratch (static: no runtime allocation) ----------------
__device__ float g_sl1[N1 * C];          // gathered slot slices of ft_1  (4 MB)
__device__ float g_sl2[N2 * C];          // gathered slot slices of ft_2  (4 MB)
__device__ int   g_perm1[N1];
__device__ int   g_perm2[N2];
__device__ int   g_start1[NTY], g_cnt1[NTY];
__device__ int   g_start2[NTY], g_cnt2[NTY];
__device__ int   g_tilePrefix[NTY + 1];
__device__ int   g_totalTiles;
__device__ int   g_is64;                 // 1 if type arrays are int64, 0 if int32

// ---------------- dtype detection --------------------------------------------
__global__ void detect_kernel(const int* __restrict__ tyraw) {
    __shared__ int sAny;
    if (threadIdx.x == 0) sAny = 0;
    __syncthreads();
    int any = 0;
    for (int i = threadIdx.x; i < 4096; i += blockDim.x)
        any |= (tyraw[2 * i + 1] != 0);
    if (any) atomicOr(&sAny, 1);
    __syncthreads();
    if (threadIdx.x == 0) g_is64 = sAny ? 0 : 1;
}

__device__ __forceinline__ int load_type(const void* ty, int i, int is64) {
    int t = is64 ? (int)((const long long*)ty)[i] : ((const int*)ty)[i];
    return t & 7;
}

// ---------------- counting sort (stable compaction per type bin) ----------------
__global__ void compact_kernel(const void* __restrict__ ty1,
                               const void* __restrict__ ty2) {
    __shared__ int sTy[N1];
    __shared__ int sBase;
    const int which = blockIdx.x >> 3;
    const int t     = blockIdx.x & 7;
    const void* ty = which ? ty2 : ty1;
    int* perm      = which ? g_perm2 : g_perm1;
    const int n = which ? N2 : N1;
    const int tid = threadIdx.x;
    const int is64 = g_is64;

    if (tid == 0) sBase = 0;
    __syncthreads();
    for (int i = tid; i < n; i += blockDim.x) sTy[i] = load_type(ty, i, is64);
    __syncthreads();

    int lc = 0;
    for (int i = tid; i < n; i += blockDim.x) lc += (sTy[i] < t) ? 1 : 0;
#pragma unroll
    for (int o = 16; o > 0; o >>= 1) lc += __shfl_down_sync(0xffffffffu, lc, o);
    if ((tid & 31) == 0) atomicAdd(&sBase, lc);
    __syncthreads();

    if (tid < 32) {
        int off = sBase;
        for (int base = 0; base < n; base += 32) {
            int i = base + tid;
            int e = (sTy[i] == t) ? 1 : 0;
            unsigned m = __ballot_sync(0xffffffffu, e != 0);
            if (e) perm[off + __popc(m & ((1u << tid) - 1u))] = i;
            off += __popc(m);
        }
        if (tid == 0) {
            if (which) { g_start2[t] = sBase; g_cnt2[t] = off - sBase; }
            else       { g_start1[t] = sBase; g_cnt1[t] = off - sBase; }
        }
    }
}

// ---------------- tile plan ----------------------------------------------------
__global__ void plan_kernel() {
    int tp = 0;
    for (int t = 0; t < NTY; t++) {
        g_tilePrefix[t] = tp;
        int gm = (g_cnt1[t] + 127) >> 7;
        int gn = (g_cnt2[t] + 127) >> 7;
        tp += gm * gn;
    }
    g_tilePrefix[NTY] = tp;
    g_totalTiles = tp;
}

// ---------------- gather slot slices --------------------------------------------
__global__ void gather_kernel(const float* __restrict__ ft1,
                              const float* __restrict__ ft2,
                              const void* __restrict__ ty1,
                              const void* __restrict__ ty2) {
    int gw   = (blockIdx.x * blockDim.x + threadIdx.x) >> 5;
    int lane = threadIdx.x & 31;
    const int is64 = g_is64;
    const float* ft;
    const void* ty;
    float* dst;
    int r;
    if (gw < N1) { ft = ft1; ty = ty1; dst = g_sl1; r = gw; }
    else         { ft = ft2; ty = ty2; dst = g_sl2; r = gw - N1; }
    int t = load_type(ty, r, is64);
    const float4* src = (const float4*)(ft + (size_t)r * D + (size_t)t * C);
    float4* d = (float4*)(dst + (size_t)r * C);
    d[lane] = src[lane];
}

// ---- helpers for the FFMA2 mainloop --------------------------------------------
// stage 4 k-values of A duplicated: As_dup[k][2*row] = As_dup[k][2*row+1] = val
__device__ __forceinline__ void stage_a_dup(float (*A)[256], int lcol, int lrow, float4 v) {
    float2 d;
    d.x = d.y = v.x; *(float2*)&A[lcol + 0][2 * lrow] = d;
    d.x = d.y = v.y; *(float2*)&A[lcol + 1][2 * lrow] = d;
    d.x = d.y = v.z; *(float2*)&A[lcol + 2][2 * lrow] = d;
    d.x = d.y = v.w; *(float2*)&A[lcol + 3][2 * lrow] = d;
}
__device__ __forceinline__ void stage_b(float (*B)[128], int lcol, int lrow, float4 v) {
    B[lcol + 0][lrow] = v.x;
    B[lcol + 1][lrow] = v.y;
    B[lcol + 2][lrow] = v.z;
    B[lcol + 3][lrow] = v.w;
}

// 8 k-steps of the 8x8 microtile via FFMA2 (acc pairs over columns)
__device__ __forceinline__ void mma8(unsigned long long acc2[8][4],
                                     float (*As_c)[256], float (*Bs_c)[128],
                                     int row0, int col0) {
#pragma unroll
    for (int k = 0; k < 8; k++) {
        ulonglong2 A0 = *(const ulonglong2*)&As_c[k][2 * row0];
        ulonglong2 A1 = *(const ulonglong2*)&As_c[k][2 * row0 + 4];
        ulonglong2 A2 = *(const ulonglong2*)&As_c[k][2 * row0 + 8];
        ulonglong2 A3 = *(const ulonglong2*)&As_c[k][2 * row0 + 12];
        ulonglong2 B0 = *(const ulonglong2*)&Bs_c[k][col0];
        ulonglong2 B1 = *(const ulonglong2*)&Bs_c[k][col0 + 4];
        unsigned long long av[8] = {A0.x, A0.y, A1.x, A1.y, A2.x, A2.y, A3.x, A3.y};
        unsigned long long bv[4] = {B0.x, B0.y, B1.x, B1.y};
#pragma unroll
        for (int i = 0; i < 8; i++)
#pragma unroll
            for (int jp = 0; jp < 4; jp++)
                FMA_F32X2(acc2[i][jp], av[i], bv[jp]);
    }
}

__device__ __forceinline__ float lo32(unsigned long long v) {
    return __uint_as_float((unsigned)v);
}
__device__ __forceinline__ float hi32(unsigned long long v) {
    return __uint_as_float((unsigned)(v >> 32));
}

// ---------------- cross GEMM: out = sl1 @ sl2^T, K=128, all 8192x8192 ----------
__global__ __launch_bounds__(256, 2)
void cross_gemm(float* __restrict__ out) {
    __shared__ __align__(16) float As[2][8][256];   // duplicated A values
    __shared__ __align__(16) float Bs[2][8][128];
    const int tid  = threadIdx.x;
    const int bi   = blockIdx.y, bj = blockIdx.x;
    const int lrow = tid >> 1;
    const int lcol = (tid & 1) << 2;
    const float* Ag = g_sl1 + (size_t)(bi * 128 + lrow) * C + lcol;
    const float* Bg = g_sl2 + (size_t)(bj * 128 + lrow) * C + lcol;
    const int row0 = (tid >> 4) << 3;
    const int col0 = (tid & 15) << 3;

    unsigned long long acc2[8][4];
#pragma unroll
    for (int i = 0; i < 8; i++)
#pragma unroll
        for (int jp = 0; jp < 4; jp++) acc2[i][jp] = 0ULL;

    stage_a_dup(As[0], lcol, lrow, *(const float4*)Ag);
    stage_b(Bs[0], lcol, lrow, *(const float4*)Bg);
    __syncthreads();

    float (*As_c)[256] = As[0], (*As_n)[256] = As[1];
    float (*Bs_c)[128] = Bs[0], (*Bs_n)[128] = Bs[1];

#pragma unroll 1
    for (int kt = 0; kt < 16; kt++) {
        float4 na, nb;
        const bool pf = (kt < 15);
        if (pf) {
            na = *(const float4*)(Ag + (kt + 1) * 8);
            nb = *(const float4*)(Bg + (kt + 1) * 8);
        }
        mma8(acc2, As_c, Bs_c, row0, col0);
        if (pf) {
            stage_a_dup(As_n, lcol, lrow, na);
            stage_b(Bs_n, lcol, lrow, nb);
            __syncthreads();
            float (*tA)[256] = As_c; As_c = As_n; As_n = tA;
            float (*tB)[128] = Bs_c; Bs_c = Bs_n; Bs_n = tB;
        }
    }

    float* obase = out + (size_t)(bi * 128 + row0) * N2 + (size_t)(bj * 128 + col0);
#pragma unroll
    for (int i = 0; i < 8; i++) {
        *(float4*)(obase + (size_t)i * N2) =
            make_float4(lo32(acc2[i][0]), hi32(acc2[i][0]), lo32(acc2[i][1]), hi32(acc2[i][1]));
        *(float4*)(obase + (size_t)i * N2 + 4) =
            make_float4(lo32(acc2[i][2]), hi32(acc2[i][2]), lo32(acc2[i][3]), hi32(acc2[i][3]));
    }
}

// ---------------- same-type block GEMM: full K=1024, overwrite same pairs ------
__global__ __launch_bounds__(256, 2)
void same_gemm(const float* __restrict__ ft1, const float* __restrict__ ft2,
               float* __restrict__ out) {
    __shared__ __align__(16) float As[2][8][256];   // duplicated A values
    __shared__ __align__(16) float Bs[2][8][128];
    __shared__ int sRowG[128];
    __shared__ int sColG[128];
    const int tid = threadIdx.x;

    const int total = g_totalTiles;
    for (int tile = blockIdx.x; tile < total; tile += gridDim.x) {
        int t = 0;
        while (tile >= g_tilePrefix[t + 1]) t++;
        const int local = tile - g_tilePrefix[t];
        const int m = g_cnt1[t], n = g_cnt2[t];
        const int gn = (n + 127) >> 7;
        const int ti = local / gn, tj = local % gn;
        const int mbase = ti * 128, nbase = tj * 128;

        __syncthreads();  // protect sRowG/sColG reuse across grid-stride tiles
        if (tid < 128) {
            int ii = mbase + tid;
            sRowG[tid] = (ii < m) ? g_perm1[g_start1[t] + ii] : -1;
            int jj = nbase + tid;
            sColG[tid] = (jj < n) ? g_perm2[g_start2[t] + jj] : -1;
        }
        __syncthreads();

        const int lrow = tid >> 1;
        const int lcol = (tid & 1) << 2;
        const int ar = sRowG[lrow];
        const int br = sColG[lrow];
        const float* Ag = ft1 + (size_t)(ar < 0 ? 0 : ar) * D + lcol;
        const float* Bg = ft2 + (size_t)(br < 0 ? 0 : br) * D + lcol;
        const int row0 = (tid >> 4) << 3;
        const int col0 = (tid & 15) << 3;

        unsigned long long acc2[8][4];
#pragma unroll
        for (int i = 0; i < 8; i++)
#pragma unroll
            for (int jp = 0; jp < 4; jp++) acc2[i][jp] = 0ULL;

        stage_a_dup(As[0], lcol, lrow, *(const float4*)Ag);
        stage_b(Bs[0], lcol, lrow, *(const float4*)Bg);
        __syncthreads();

        float (*As_c)[256] = As[0], (*As_n)[256] = As[1];
        float (*Bs_c)[128] = Bs[0], (*Bs_n)[128] = Bs[1];

#pragma unroll 1
        for (int kt = 0; kt < 128; kt++) {
            float4 na, nb;
            const bool pf = (kt < 127);
            if (pf) {
                na = *(const float4*)(Ag + (kt + 1) * 8);
                nb = *(const float4*)(Bg + (kt + 1) * 8);
            }
            mma8(acc2, As_c, Bs_c, row0, col0);
            if (pf) {
                stage_a_dup(As_n, lcol, lrow, na);
                stage_b(Bs_n, lcol, lrow, nb);
                __syncthreads();
                float (*tA)[256] = As_c; As_c = As_n; As_n = tA;
                float (*tB)[128] = Bs_c; Bs_c = Bs_n; Bs_n = tB;
            }
        }

        // scattered epilogue
        int cols[8];
#pragma unroll
        for (int j = 0; j < 8; j++) cols[j] = sColG[col0 + j];
#pragma unroll
        for (int i = 0; i < 8; i++) {
            int r = sRowG[row0 + i];
            if (r >= 0) {
                float* orow = out + (size_t)r * N2;
                float v[8];
#pragma unroll
                for (int jp = 0; jp < 4; jp++) {
                    v[2 * jp]     = lo32(acc2[i][jp]);
                    v[2 * jp + 1] = hi32(acc2[i][jp]);
                }
#pragma unroll
                for (int j = 0; j < 8; j++)
                    if (cols[j] >= 0) orow[cols[j]] = v[j];
            }
        }
    }
}

// -------------------------------- launch ---------------------------------------
extern "C" void kernel_launch(void* const* d_in, const int* in_sizes, int n_in,
                              void* d_out, int out_size) {
    const float* ft1 = (const float*)d_in[0];
    const float* ft2 = (const float*)d_in[1];
    const void*  ty1 = d_in[2];
    const void*  ty2 = d_in[3];
    float* out = (float*)d_out;

    detect_kernel<<<1, 256>>>((const int*)ty1);
    compact_kernel<<<16, 256>>>(ty1, ty2);
    plan_kernel<<<1, 1>>>();
    gather_kernel<<<(N1 + N2) / 8, 256>>>(ft1, ft2, ty1, ty2);

    dim3 gc(N2 / 128, N1 / 128);
    cross_gemm<<<gc, 256>>>(out);             // writes every output element (cross)
    same_gemm<<<1024, 256>>>(ft1, ft2, out);  // overwrites same-type pairs (full)
}